// round 1
// baseline (speedup 1.0000x reference)
#include <cuda_runtime.h>
#include <cuda_bf16.h>
#include <math.h>

// Problem dims (fixed)
#define TB    16          // batch
#define LL    1024        // tokens per sample
#define TT    (TB*LL)     // 16384 tokens
#define CLAT  16
#define CC    512
#define NHH   8
#define HDD   64
#define NBLK  4
#define CFF   (4*CC)      // 2048
#define OUTC  8

// -------------------- scratch (device globals, no allocation) --------------------
__device__ float g_h   [TT*CC];     // residual stream           32 MB
__device__ float g_a   [TT*CC];     // LN output                 32 MB
__device__ float g_qkv [TT*3*CC];   // qkv                       96 MB
__device__ float g_o   [TT*CC];     // attention out             32 MB
__device__ float g_m   [TT*CFF];    // fc1 out                  128 MB
__device__ float g_pool[TB*2*CC];   // pooled features

// -------------------- generic SGEMM: C = A[MxK] @ B[KxN] + bias (+epilogue) ------
// EPI: 0 = none, 1 = gelu(tanh approx), 2 = residual add (C = R + v)
#define BM 128
#define BN 64
#define BK 16
#define TM 8
#define TN 4

__device__ __forceinline__ float gelu_tanh(float x) {
    float x3 = x * x * x;
    return 0.5f * x * (1.0f + tanhf(0.7978845608028654f * (x + 0.044715f * x3)));
}

template<int EPI>
__global__ __launch_bounds__(256)
void gemm_kernel(const float* __restrict__ A, const float* __restrict__ B,
                 const float* __restrict__ bias, float* __restrict__ C,
                 const float* __restrict__ R, int M, int N, int K)
{
    __shared__ float As[BK][BM];
    __shared__ float Bs[BK][BN];

    const int tid = threadIdx.x;
    const int tx  = tid & 15;        // 16 col groups
    const int ty  = tid >> 4;        // 16 row groups
    const int row0 = blockIdx.y * BM + ty * TM;
    const int col0 = blockIdx.x * BN + tx * TN;

    float acc[TM][TN];
    #pragma unroll
    for (int i = 0; i < TM; i++)
        #pragma unroll
        for (int j = 0; j < TN; j++) acc[i][j] = 0.f;

    for (int kt = 0; kt < K; kt += BK) {
        // load A tile (BM x BK) transposed into As[BK][BM]
        #pragma unroll 4
        for (int i = tid; i < BM*BK; i += 256) {
            int r = i >> 4;          // / BK
            int c = i & 15;
            As[c][r] = A[(blockIdx.y * BM + r) * K + kt + c];
        }
        // load B tile (BK x BN)
        #pragma unroll 2
        for (int i = tid; i < BK*BN; i += 256) {
            int r = i >> 6;          // / BN
            int c = i & 63;
            Bs[r][c] = B[(kt + r) * N + blockIdx.x * BN + c];
        }
        __syncthreads();

        #pragma unroll
        for (int k = 0; k < BK; k++) {
            float a[TM], b[TN];
            #pragma unroll
            for (int i = 0; i < TM; i++) a[i] = As[k][ty * TM + i];
            #pragma unroll
            for (int j = 0; j < TN; j++) b[j] = Bs[k][tx * TN + j];
            #pragma unroll
            for (int i = 0; i < TM; i++)
                #pragma unroll
                for (int j = 0; j < TN; j++)
                    acc[i][j] += a[i] * b[j];
        }
        __syncthreads();
    }

    #pragma unroll
    for (int i = 0; i < TM; i++) {
        int r = row0 + i;
        #pragma unroll
        for (int j = 0; j < TN; j++) {
            int c = col0 + j;
            float v = acc[i][j] + bias[c];
            size_t idx = (size_t)r * N + c;
            if (EPI == 1)      C[idx] = gelu_tanh(v);
            else if (EPI == 2) C[idx] = R[idx] + v;
            else               C[idx] = v;
        }
    }
}

// -------------------- flash attention (fp32, online softmax) --------------------
// grid: (q_tiles=16, heads=8, batch=16), block 256
// Q tile: 64 rows x 64 dims; key tiles of 32. Static smem < 48 KB.
__global__ __launch_bounds__(256)
void flash_kernel(const float* __restrict__ qkv, float* __restrict__ o)
{
    __shared__ float Qs[64 * 68];    // 17408 B
    __shared__ float Ks[32 * 68];    //  8704 B
    __shared__ float Vs[32 * 68];    //  8704 B
    __shared__ float Ps[64 * 36];    //  9216 B   (total 44032 B)

    const int tid = threadIdx.x;
    const int r   = tid >> 2;        // 0..63  query row in tile
    const int g   = tid & 3;         // 4-lane group per row
    const int b   = blockIdx.z;
    const int h   = blockIdx.y;
    const int qt  = blockIdx.x;

    // load Q tile
    for (int i = tid; i < 64 * 64; i += 256) {
        int rr = i >> 6, d = i & 63;
        Qs[rr * 68 + d] = qkv[((size_t)(b * LL + qt * 64 + rr)) * 1536 + h * 64 + d];
    }

    float m_run = -INFINITY, l_run = 0.f;
    float oacc[16];
    #pragma unroll
    for (int j = 0; j < 16; j++) oacc[j] = 0.f;

    const float4* Q4 = (const float4*)(Qs + r * 68);

    for (int kt = 0; kt < 32; kt++) {
        __syncthreads();   // protects Q (iter 0) and Ks/Vs/Ps reuse
        for (int i = tid; i < 32 * 64; i += 256) {
            int rr = i >> 6, d = i & 63;
            size_t t = ((size_t)(b * LL + kt * 32 + rr)) * 1536 + h * 64 + d;
            Ks[rr * 68 + d] = qkv[t + 512];
            Vs[rr * 68 + d] = qkv[t + 1024];
        }
        __syncthreads();

        // scores for this thread's 8 keys: kk = g*8 + j
        float s[8];
        #pragma unroll
        for (int j = 0; j < 8; j++) s[j] = 0.f;
        #pragma unroll
        for (int d4 = 0; d4 < 16; d4++) {
            float4 q = Q4[d4];
            #pragma unroll
            for (int j = 0; j < 8; j++) {
                float4 kv = *(const float4*)(Ks + (g * 8 + j) * 68 + d4 * 4);
                s[j] += q.x * kv.x + q.y * kv.y + q.z * kv.z + q.w * kv.w;
            }
        }
        float mloc = -INFINITY;
        #pragma unroll
        for (int j = 0; j < 8; j++) { s[j] *= 0.125f; mloc = fmaxf(mloc, s[j]); }
        mloc = fmaxf(mloc, __shfl_xor_sync(0xffffffffu, mloc, 1));
        mloc = fmaxf(mloc, __shfl_xor_sync(0xffffffffu, mloc, 2));
        float m_new = fmaxf(m_run, mloc);
        float corr  = __expf(m_run - m_new);         // 0 on first iter (m_run=-inf)
        float psum  = 0.f;
        #pragma unroll
        for (int j = 0; j < 8; j++) {
            float p = __expf(s[j] - m_new);
            Ps[r * 36 + g * 8 + j] = p;
            psum += p;
        }
        psum += __shfl_xor_sync(0xffffffffu, psum, 1);
        psum += __shfl_xor_sync(0xffffffffu, psum, 2);
        l_run = l_run * corr + psum;
        m_run = m_new;
        #pragma unroll
        for (int j = 0; j < 16; j++) oacc[j] *= corr;
        __syncthreads();

        // PV: each thread accumulates its 16 output dims (cols g*16 .. g*16+15)
        for (int kk = 0; kk < 32; kk++) {
            float p = Ps[r * 36 + kk];
            const float4* V4 = (const float4*)(Vs + kk * 68 + g * 16);
            #pragma unroll
            for (int j4 = 0; j4 < 4; j4++) {
                float4 v = V4[j4];
                oacc[j4 * 4 + 0] += p * v.x;
                oacc[j4 * 4 + 1] += p * v.y;
                oacc[j4 * 4 + 2] += p * v.z;
                oacc[j4 * 4 + 3] += p * v.w;
            }
        }
    }

    float inv = 1.f / l_run;
    size_t t = (size_t)(b * LL + qt * 64 + r);
    #pragma unroll
    for (int j = 0; j < 16; j++)
        o[t * CC + h * 64 + g * 16 + j] = oacc[j] * inv;
}

// -------------------- layer norm (row of 512), optional affine ------------------
__global__ __launch_bounds__(256)
void ln_kernel(const float* __restrict__ x, const float* __restrict__ sc,
               const float* __restrict__ bi, float* __restrict__ y, int affine)
{
    __shared__ float red[8];
    const int row = blockIdx.x;
    const int tid = threadIdx.x;
    const float* xr = x + (size_t)row * CC;

    float v0 = xr[tid], v1 = xr[tid + 256];
    float t = v0 + v1;
    #pragma unroll
    for (int off = 16; off; off >>= 1) t += __shfl_xor_sync(0xffffffffu, t, off);
    if ((tid & 31) == 0) red[tid >> 5] = t;
    __syncthreads();
    float tot = 0.f;
    #pragma unroll
    for (int i = 0; i < 8; i++) tot += red[i];
    float mean = tot * (1.f / 512.f);
    __syncthreads();            // red about to be reused

    float d0 = v0 - mean, d1 = v1 - mean;
    t = d0 * d0 + d1 * d1;
    #pragma unroll
    for (int off = 16; off; off >>= 1) t += __shfl_xor_sync(0xffffffffu, t, off);
    if ((tid & 31) == 0) red[tid >> 5] = t;
    __syncthreads();
    tot = 0.f;
    #pragma unroll
    for (int i = 0; i < 8; i++) tot += red[i];
    float var = tot * (1.f / 512.f);
    float inv = rsqrtf(var + 1e-5f);

    float r0 = d0 * inv, r1 = d1 * inv;
    if (affine) {
        r0 = r0 * sc[tid]       + bi[tid];
        r1 = r1 * sc[tid + 256] + bi[tid + 256];
    }
    y[(size_t)row * CC + tid]       = r0;
    y[(size_t)row * CC + tid + 256] = r1;
}

// -------------------- segmented mean+max pool -----------------------------------
// grid (B, 4), block 128: one thread per channel
__global__ __launch_bounds__(128)
void pool_kernel(const float* __restrict__ hf, float* __restrict__ g)
{
    const int b = blockIdx.x;
    const int c = blockIdx.y * 128 + threadIdx.x;
    const float* p = hf + (size_t)b * LL * CC + c;
    float sum = 0.f, mx = -INFINITY;
    for (int l = 0; l < LL; l++) {
        float v = p[(size_t)l * CC];
        sum += v;
        mx = fmaxf(mx, v);
    }
    g[b * (2 * CC) + c]      = sum * (1.f / (float)LL);
    g[b * (2 * CC) + CC + c] = mx;
}

// -------------------- head: out[16,8] = g[16,1024] @ W[1024,8] + b --------------
__global__ __launch_bounds__(128)
void head_kernel(const float* __restrict__ g, const float* __restrict__ W,
                 const float* __restrict__ bh, float* __restrict__ out)
{
    const int tid = threadIdx.x;          // 128 = 16*8
    const int b = tid >> 3, o = tid & 7;
    float acc = bh[o];
    const float* gr = g + b * 1024;
    for (int k = 0; k < 1024; k++) acc += gr[k] * W[k * 8 + o];
    out[b * 8 + o] = acc;
}

// -------------------- host launch -----------------------------------------------
static float* sym_addr(const void* sym) {
    void* p = nullptr;
    cudaGetSymbolAddress(&p, sym);
    return (float*)p;
}

extern "C" void kernel_launch(void* const* d_in, const int* in_sizes, int n_in,
                              void* d_out, int out_size)
{
    const float* feats  = (const float*)d_in[0];
    // d_in[1] = batch_idx (int32): segments are provably equal-size (arange//L); unused.
    const float* W_in   = (const float*)d_in[2];
    const float* b_in   = (const float*)d_in[3];
    const float* ln1_s  = (const float*)d_in[4];
    const float* ln1_b  = (const float*)d_in[5];
    const float* W_qkv  = (const float*)d_in[6];
    const float* b_qkv  = (const float*)d_in[7];
    const float* W_o    = (const float*)d_in[8];
    const float* b_o    = (const float*)d_in[9];
    const float* ln2_s  = (const float*)d_in[10];
    const float* ln2_b  = (const float*)d_in[11];
    const float* W_fc1  = (const float*)d_in[12];
    const float* b_fc1  = (const float*)d_in[13];
    const float* W_fc2  = (const float*)d_in[14];
    const float* b_fc2  = (const float*)d_in[15];
    const float* W_head = (const float*)d_in[16];
    const float* b_head = (const float*)d_in[17];
    float* out = (float*)d_out;

    float* h    = sym_addr(g_h);
    float* a    = sym_addr(g_a);
    float* qkv  = sym_addr(g_qkv);
    float* attn = sym_addr(g_o);
    float* ffn  = sym_addr(g_m);
    float* pool = sym_addr(g_pool);

    // input projection: h = feats @ W_in + b_in   [16384,16]x[16,512]
    gemm_kernel<0><<<dim3(CC / BN, TT / BM), 256>>>(feats, W_in, b_in, h, nullptr, TT, CC, CLAT);

    for (int i = 0; i < NBLK; i++) {
        // a = LN(h) * s1 + b1
        ln_kernel<<<TT, 256>>>(h, ln1_s + i * CC, ln1_b + i * CC, a, 1);
        // qkv = a @ W_qkv[i] + b_qkv[i]   [16384,512]x[512,1536]
        gemm_kernel<0><<<dim3((3 * CC) / BN, TT / BM), 256>>>(
            a, W_qkv + (size_t)i * CC * 3 * CC, b_qkv + i * 3 * CC, qkv, nullptr, TT, 3 * CC, CC);
        // attention
        flash_kernel<<<dim3(LL / 64, NHH, TB), 256>>>(qkv, attn);
        // h = h + attn @ W_o[i] + b_o[i]
        gemm_kernel<2><<<dim3(CC / BN, TT / BM), 256>>>(
            attn, W_o + (size_t)i * CC * CC, b_o + i * CC, h, h, TT, CC, CC);
        // a = LN(h) * s2 + b2
        ln_kernel<<<TT, 256>>>(h, ln2_s + i * CC, ln2_b + i * CC, a, 1);
        // ffn = gelu(a @ W_fc1[i] + b_fc1[i])    [16384,512]x[512,2048]
        gemm_kernel<1><<<dim3(CFF / BN, TT / BM), 256>>>(
            a, W_fc1 + (size_t)i * CC * CFF, b_fc1 + i * CFF, ffn, nullptr, TT, CFF, CC);
        // h = h + ffn @ W_fc2[i] + b_fc2[i]      [16384,2048]x[2048,512]
        gemm_kernel<2><<<dim3(CC / BN, TT / BM), 256>>>(
            ffn, W_fc2 + (size_t)i * CFF * CC, b_fc2 + i * CC, h, h, TT, CC, CFF);
    }

    // final LN (no affine) -> a
    ln_kernel<<<TT, 256>>>(h, nullptr, nullptr, a, 0);
    // segmented mean+max pool -> pool[16, 1024]
    pool_kernel<<<dim3(TB, CC / 128), 128>>>(a, pool);
    // head
    head_kernel<<<1, 128>>>(pool, W_head, b_head, out);
    (void)in_sizes; (void)n_in; (void)out_size;
}

// round 2
// speedup vs baseline: 1.4252x; 1.4252x over previous
#include <cuda_runtime.h>
#include <cuda_bf16.h>
#include <math.h>
#include <stdint.h>

// Problem dims (fixed)
#define TB    16          // batch
#define LL    1024        // tokens per sample
#define TT    (TB*LL)     // 16384 tokens
#define CLAT  16
#define CC    512
#define NHH   8
#define HDD   64
#define NBLK  4
#define CFF   (4*CC)      // 2048
#define OUTC  8

// -------------------- scratch (device globals, no allocation) --------------------
__device__ float g_h   [TT*CC];     // residual stream           32 MB
__device__ float g_a   [TT*CC];     // LN output                 32 MB
__device__ float g_qkv [TT*3*CC];   // qkv                       96 MB
__device__ float g_o   [TT*CC];     // attention out             32 MB
__device__ float g_m   [TT*CFF];    // fc1 out                  128 MB
__device__ float g_pool[TB*2*CC];   // pooled features

__device__ __forceinline__ float gelu_tanh(float x) {
    float x3 = x * x * x;
    return 0.5f * x * (1.0f + tanhf(0.7978845608028654f * (x + 0.044715f * x3)));
}

// ==================== TF32 tensor-core GEMM ====================
// C[M,N] = A[M,K] @ B[K,N] + bias (+epilogue). M%128==0, N%128==0, K%16==0.
// EPI: 0 = none, 1 = gelu, 2 = residual add (C = R + v)
// CTA tile 128x128x16, 8 warps (4M x 2N), warp tile 32x64, mma.m16n8k8.tf32.

__device__ __forceinline__ uint32_t f2tf32(float f) {
    uint32_t u;
    asm("cvt.rna.tf32.f32 %0, %1;" : "=r"(u) : "f"(f));
    return u;
}

__device__ __forceinline__ void cp_async16(uint32_t saddr, const void* gptr) {
    asm volatile("cp.async.cg.shared.global [%0], [%1], 16;" :: "r"(saddr), "l"(gptr));
}
__device__ __forceinline__ void cp_commit() {
    asm volatile("cp.async.commit_group;");
}
__device__ __forceinline__ void cp_wait0() {
    asm volatile("cp.async.wait_group 0;");
}

__device__ __forceinline__ void mma_tf32(float* d, const uint32_t* a, const uint32_t* b) {
    asm volatile(
        "mma.sync.aligned.m16n8k8.row.col.f32.tf32.tf32.f32 "
        "{%0,%1,%2,%3}, {%4,%5,%6,%7}, {%8,%9}, {%0,%1,%2,%3};"
        : "+f"(d[0]), "+f"(d[1]), "+f"(d[2]), "+f"(d[3])
        : "r"(a[0]), "r"(a[1]), "r"(a[2]), "r"(a[3]), "r"(b[0]), "r"(b[1]));
}

#define APAD 20   // A smem row stride (floats): conflict-free for frag loads
#define BPAD 136  // B smem row stride (floats): conflict-free for frag loads

template<int EPI>
__global__ __launch_bounds__(256, 2)
void gemm_tf32_kernel(const float* __restrict__ A, const float* __restrict__ B,
                      const float* __restrict__ bias, float* __restrict__ C,
                      const float* __restrict__ R, int M, int N, int K)
{
    __shared__ float As[2][128][APAD];   // 2*128*20*4 = 20480 B
    __shared__ float Bs[2][16][BPAD];    // 2*16*136*4 = 17408 B

    const int tid    = threadIdx.x;
    const int lane   = tid & 31;
    const int warp   = tid >> 5;
    const int warp_m = warp & 3;   // 0..3
    const int warp_n = warp >> 2;  // 0..1
    const int g      = lane >> 2;  // 0..7
    const int t      = lane & 3;   // 0..3

    const int rowbase = blockIdx.y * 128;
    const int colbase = blockIdx.x * 128;
    const int nk = K >> 4;

    float acc[2][8][4];
    #pragma unroll
    for (int mf = 0; mf < 2; mf++)
        #pragma unroll
        for (int nf = 0; nf < 8; nf++)
            #pragma unroll
            for (int j = 0; j < 4; j++) acc[mf][nf][j] = 0.f;

    auto load_tile = [&](int kt, int buf) {
        const float* Ag = A + (size_t)rowbase * K + kt * 16;
        #pragma unroll
        for (int i = 0; i < 2; i++) {
            int c   = tid + i * 256;       // 0..511
            int row = c >> 2;
            int kq  = c & 3;
            uint32_t s = (uint32_t)__cvta_generic_to_shared(&As[buf][row][kq * 4]);
            cp_async16(s, Ag + (size_t)row * K + kq * 4);
        }
        const float* Bg = B + (size_t)(kt * 16) * N + colbase;
        #pragma unroll
        for (int i = 0; i < 2; i++) {
            int c    = tid + i * 256;      // 0..511
            int krow = c >> 5;
            int nq   = c & 31;
            uint32_t s = (uint32_t)__cvta_generic_to_shared(&Bs[buf][krow][nq * 4]);
            cp_async16(s, Bg + (size_t)krow * N + nq * 4);
        }
    };

    load_tile(0, 0);
    cp_commit();

    for (int kt = 0; kt < nk; kt++) {
        cp_wait0();
        __syncthreads();
        if (kt + 1 < nk) {
            load_tile(kt + 1, (kt + 1) & 1);
            cp_commit();
        }

        const int buf = kt & 1;
        const float (*Asb)[APAD] = As[buf];
        const float (*Bsb)[BPAD] = Bs[buf];

        #pragma unroll
        for (int ks = 0; ks < 2; ks++) {
            const int k0 = ks * 8;
            uint32_t au[2][4];
            #pragma unroll
            for (int mf = 0; mf < 2; mf++) {
                const int mr = warp_m * 32 + mf * 16;
                au[mf][0] = f2tf32(Asb[mr + g    ][k0 + t    ]);
                au[mf][1] = f2tf32(Asb[mr + g + 8][k0 + t    ]);
                au[mf][2] = f2tf32(Asb[mr + g    ][k0 + t + 4]);
                au[mf][3] = f2tf32(Asb[mr + g + 8][k0 + t + 4]);
            }
            uint32_t bu[8][2];
            #pragma unroll
            for (int nf = 0; nf < 8; nf++) {
                const int nc = warp_n * 64 + nf * 8 + g;
                bu[nf][0] = f2tf32(Bsb[k0 + t    ][nc]);
                bu[nf][1] = f2tf32(Bsb[k0 + t + 4][nc]);
            }
            #pragma unroll
            for (int mf = 0; mf < 2; mf++)
                #pragma unroll
                for (int nf = 0; nf < 8; nf++)
                    mma_tf32(acc[mf][nf], au[mf], bu[nf]);
        }
    }

    // epilogue
    #pragma unroll
    for (int mf = 0; mf < 2; mf++) {
        const int r0 = rowbase + warp_m * 32 + mf * 16 + g;
        #pragma unroll
        for (int nf = 0; nf < 8; nf++) {
            const int col = colbase + warp_n * 64 + nf * 8 + t * 2;
            const float b0 = __ldg(bias + col);
            const float b1 = __ldg(bias + col + 1);
            #pragma unroll
            for (int half = 0; half < 2; half++) {
                const int r = r0 + half * 8;
                float v0 = acc[mf][nf][half * 2 + 0] + b0;
                float v1 = acc[mf][nf][half * 2 + 1] + b1;
                size_t idx = (size_t)r * N + col;
                if (EPI == 1) { v0 = gelu_tanh(v0); v1 = gelu_tanh(v1); }
                else if (EPI == 2) {
                    float2 rr = *(const float2*)(R + idx);
                    v0 += rr.x; v1 += rr.y;
                }
                *(float2*)(C + idx) = make_float2(v0, v1);
            }
        }
    }
}

// -------------------- small SIMT GEMM for input projection (K=16) ----------------
#define BM 128
#define BN 64
#define BK 16
#define TMx 8
#define TNx 4

__global__ __launch_bounds__(256)
void gemm_simt_kernel(const float* __restrict__ A, const float* __restrict__ B,
                      const float* __restrict__ bias, float* __restrict__ C,
                      int M, int N, int K)
{
    __shared__ float As[BK][BM];
    __shared__ float Bs[BK][BN];

    const int tid = threadIdx.x;
    const int tx  = tid & 15;
    const int ty  = tid >> 4;
    const int row0 = blockIdx.y * BM + ty * TMx;
    const int col0 = blockIdx.x * BN + tx * TNx;

    float acc[TMx][TNx];
    #pragma unroll
    for (int i = 0; i < TMx; i++)
        #pragma unroll
        for (int j = 0; j < TNx; j++) acc[i][j] = 0.f;

    for (int kt = 0; kt < K; kt += BK) {
        #pragma unroll 4
        for (int i = tid; i < BM*BK; i += 256) {
            int r = i >> 4, c = i & 15;
            As[c][r] = A[(size_t)(blockIdx.y * BM + r) * K + kt + c];
        }
        #pragma unroll 2
        for (int i = tid; i < BK*BN; i += 256) {
            int r = i >> 6, c = i & 63;
            Bs[r][c] = B[(size_t)(kt + r) * N + blockIdx.x * BN + c];
        }
        __syncthreads();
        #pragma unroll
        for (int k = 0; k < BK; k++) {
            float a[TMx], b[TNx];
            #pragma unroll
            for (int i = 0; i < TMx; i++) a[i] = As[k][ty * TMx + i];
            #pragma unroll
            for (int j = 0; j < TNx; j++) b[j] = Bs[k][tx * TNx + j];
            #pragma unroll
            for (int i = 0; i < TMx; i++)
                #pragma unroll
                for (int j = 0; j < TNx; j++)
                    acc[i][j] += a[i] * b[j];
        }
        __syncthreads();
    }
    #pragma unroll
    for (int i = 0; i < TMx; i++)
        #pragma unroll
        for (int j = 0; j < TNx; j++)
            C[(size_t)(row0 + i) * N + col0 + j] = acc[i][j] + bias[col0 + j];
}

// -------------------- flash attention (fp32, online softmax) --------------------
__global__ __launch_bounds__(256)
void flash_kernel(const float* __restrict__ qkv, float* __restrict__ o)
{
    __shared__ float Qs[64 * 68];
    __shared__ float Ks[32 * 68];
    __shared__ float Vs[32 * 68];
    __shared__ float Ps[64 * 36];

    const int tid = threadIdx.x;
    const int r   = tid >> 2;
    const int g   = tid & 3;
    const int b   = blockIdx.z;
    const int h   = blockIdx.y;
    const int qt  = blockIdx.x;

    for (int i = tid; i < 64 * 64; i += 256) {
        int rr = i >> 6, d = i & 63;
        Qs[rr * 68 + d] = qkv[((size_t)(b * LL + qt * 64 + rr)) * 1536 + h * 64 + d];
    }

    float m_run = -INFINITY, l_run = 0.f;
    float oacc[16];
    #pragma unroll
    for (int j = 0; j < 16; j++) oacc[j] = 0.f;

    const float4* Q4 = (const float4*)(Qs + r * 68);

    for (int kt = 0; kt < 32; kt++) {
        __syncthreads();
        for (int i = tid; i < 32 * 64; i += 256) {
            int rr = i >> 6, d = i & 63;
            size_t tix = ((size_t)(b * LL + kt * 32 + rr)) * 1536 + h * 64 + d;
            Ks[rr * 68 + d] = qkv[tix + 512];
            Vs[rr * 68 + d] = qkv[tix + 1024];
        }
        __syncthreads();

        float s[8];
        #pragma unroll
        for (int j = 0; j < 8; j++) s[j] = 0.f;
        #pragma unroll
        for (int d4 = 0; d4 < 16; d4++) {
            float4 q = Q4[d4];
            #pragma unroll
            for (int j = 0; j < 8; j++) {
                float4 kv = *(const float4*)(Ks + (g * 8 + j) * 68 + d4 * 4);
                s[j] += q.x * kv.x + q.y * kv.y + q.z * kv.z + q.w * kv.w;
            }
        }
        float mloc = -INFINITY;
        #pragma unroll
        for (int j = 0; j < 8; j++) { s[j] *= 0.125f; mloc = fmaxf(mloc, s[j]); }
        mloc = fmaxf(mloc, __shfl_xor_sync(0xffffffffu, mloc, 1));
        mloc = fmaxf(mloc, __shfl_xor_sync(0xffffffffu, mloc, 2));
        float m_new = fmaxf(m_run, mloc);
        float corr  = __expf(m_run - m_new);
        float psum  = 0.f;
        #pragma unroll
        for (int j = 0; j < 8; j++) {
            float p = __expf(s[j] - m_new);
            Ps[r * 36 + g * 8 + j] = p;
            psum += p;
        }
        psum += __shfl_xor_sync(0xffffffffu, psum, 1);
        psum += __shfl_xor_sync(0xffffffffu, psum, 2);
        l_run = l_run * corr + psum;
        m_run = m_new;
        #pragma unroll
        for (int j = 0; j < 16; j++) oacc[j] *= corr;
        __syncthreads();

        for (int kk = 0; kk < 32; kk++) {
            float p = Ps[r * 36 + kk];
            const float4* V4 = (const float4*)(Vs + kk * 68 + g * 16);
            #pragma unroll
            for (int j4 = 0; j4 < 4; j4++) {
                float4 v = V4[j4];
                oacc[j4 * 4 + 0] += p * v.x;
                oacc[j4 * 4 + 1] += p * v.y;
                oacc[j4 * 4 + 2] += p * v.z;
                oacc[j4 * 4 + 3] += p * v.w;
            }
        }
    }

    float inv = 1.f / l_run;
    size_t tix = (size_t)(b * LL + qt * 64 + r);
    #pragma unroll
    for (int j = 0; j < 16; j++)
        o[tix * CC + h * 64 + g * 16 + j] = oacc[j] * inv;
}

// -------------------- layer norm (row of 512), optional affine ------------------
__global__ __launch_bounds__(256)
void ln_kernel(const float* __restrict__ x, const float* __restrict__ sc,
               const float* __restrict__ bi, float* __restrict__ y, int affine)
{
    __shared__ float red[8];
    const int row = blockIdx.x;
    const int tid = threadIdx.x;
    const float* xr = x + (size_t)row * CC;

    float v0 = xr[tid], v1 = xr[tid + 256];
    float t = v0 + v1;
    #pragma unroll
    for (int off = 16; off; off >>= 1) t += __shfl_xor_sync(0xffffffffu, t, off);
    if ((tid & 31) == 0) red[tid >> 5] = t;
    __syncthreads();
    float tot = 0.f;
    #pragma unroll
    for (int i = 0; i < 8; i++) tot += red[i];
    float mean = tot * (1.f / 512.f);
    __syncthreads();

    float d0 = v0 - mean, d1 = v1 - mean;
    t = d0 * d0 + d1 * d1;
    #pragma unroll
    for (int off = 16; off; off >>= 1) t += __shfl_xor_sync(0xffffffffu, t, off);
    if ((tid & 31) == 0) red[tid >> 5] = t;
    __syncthreads();
    tot = 0.f;
    #pragma unroll
    for (int i = 0; i < 8; i++) tot += red[i];
    float var = tot * (1.f / 512.f);
    float inv = rsqrtf(var + 1e-5f);

    float r0 = d0 * inv, r1 = d1 * inv;
    if (affine) {
        r0 = r0 * sc[tid]       + bi[tid];
        r1 = r1 * sc[tid + 256] + bi[tid + 256];
    }
    y[(size_t)row * CC + tid]       = r0;
    y[(size_t)row * CC + tid + 256] = r1;
}

// -------------------- segmented mean+max pool -----------------------------------
__global__ __launch_bounds__(128)
void pool_kernel(const float* __restrict__ hf, float* __restrict__ gp)
{
    const int b = blockIdx.x;
    const int c = blockIdx.y * 128 + threadIdx.x;
    const float* p = hf + (size_t)b * LL * CC + c;
    float sum = 0.f, mx = -INFINITY;
    for (int l = 0; l < LL; l++) {
        float v = p[(size_t)l * CC];
        sum += v;
        mx = fmaxf(mx, v);
    }
    gp[b * (2 * CC) + c]      = sum * (1.f / (float)LL);
    gp[b * (2 * CC) + CC + c] = mx;
}

// -------------------- head ------------------------------------------------------
__global__ __launch_bounds__(128)
void head_kernel(const float* __restrict__ gp, const float* __restrict__ W,
                 const float* __restrict__ bh, float* __restrict__ out)
{
    const int tid = threadIdx.x;
    const int b = tid >> 3, o = tid & 7;
    float acc = bh[o];
    const float* gr = gp + b * 1024;
    for (int k = 0; k < 1024; k++) acc += gr[k] * W[k * 8 + o];
    out[b * 8 + o] = acc;
}

// -------------------- host launch -----------------------------------------------
static float* sym_addr(const void* sym) {
    void* p = nullptr;
    cudaGetSymbolAddress(&p, sym);
    return (float*)p;
}

extern "C" void kernel_launch(void* const* d_in, const int* in_sizes, int n_in,
                              void* d_out, int out_size)
{
    const float* feats  = (const float*)d_in[0];
    // d_in[1] = batch_idx (equal segments by construction) — unused
    const float* W_in   = (const float*)d_in[2];
    const float* b_in   = (const float*)d_in[3];
    const float* ln1_s  = (const float*)d_in[4];
    const float* ln1_b  = (const float*)d_in[5];
    const float* W_qkv  = (const float*)d_in[6];
    const float* b_qkv  = (const float*)d_in[7];
    const float* W_o    = (const float*)d_in[8];
    const float* b_o    = (const float*)d_in[9];
    const float* ln2_s  = (const float*)d_in[10];
    const float* ln2_b  = (const float*)d_in[11];
    const float* W_fc1  = (const float*)d_in[12];
    const float* b_fc1  = (const float*)d_in[13];
    const float* W_fc2  = (const float*)d_in[14];
    const float* b_fc2  = (const float*)d_in[15];
    const float* W_head = (const float*)d_in[16];
    const float* b_head = (const float*)d_in[17];
    float* out = (float*)d_out;

    float* h    = sym_addr(g_h);
    float* a    = sym_addr(g_a);
    float* qkv  = sym_addr(g_qkv);
    float* attn = sym_addr(g_o);
    float* ffn  = sym_addr(g_m);
    float* pool = sym_addr(g_pool);

    // input projection: h = feats @ W_in + b_in   [16384,16]x[16,512]
    gemm_simt_kernel<<<dim3(CC / BN, TT / BM), 256>>>(feats, W_in, b_in, h, TT, CC, CLAT);

    for (int i = 0; i < NBLK; i++) {
        ln_kernel<<<TT, 256>>>(h, ln1_s + i * CC, ln1_b + i * CC, a, 1);
        gemm_tf32_kernel<0><<<dim3((3 * CC) / 128, TT / 128), 256>>>(
            a, W_qkv + (size_t)i * CC * 3 * CC, b_qkv + i * 3 * CC, qkv, nullptr, TT, 3 * CC, CC);
        flash_kernel<<<dim3(LL / 64, NHH, TB), 256>>>(qkv, attn);
        gemm_tf32_kernel<2><<<dim3(CC / 128, TT / 128), 256>>>(
            attn, W_o + (size_t)i * CC * CC, b_o + i * CC, h, h, TT, CC, CC);
        ln_kernel<<<TT, 256>>>(h, ln2_s + i * CC, ln2_b + i * CC, a, 1);
        gemm_tf32_kernel<1><<<dim3(CFF / 128, TT / 128), 256>>>(
            a, W_fc1 + (size_t)i * CC * CFF, b_fc1 + i * CFF, ffn, nullptr, TT, CFF, CC);
        gemm_tf32_kernel<2><<<dim3(CC / 128, TT / 128), 256>>>(
            ffn, W_fc2 + (size_t)i * CFF * CC, b_fc2 + i * CC, h, h, TT, CC, CFF);
    }

    ln_kernel<<<TT, 256>>>(h, nullptr, nullptr, a, 0);
    pool_kernel<<<dim3(TB, CC / 128), 128>>>(a, pool);
    head_kernel<<<1, 128>>>(pool, W_head, b_head, out);
    (void)in_sizes; (void)n_in; (void)out_size;
}

// round 4
// speedup vs baseline: 13.5029x; 9.4742x over previous
#include <cuda_runtime.h>
#include <cuda_fp16.h>
#include <math.h>
#include <stdint.h>

// Problem dims (fixed)
#define TB    16
#define LL    1024
#define TT    (TB*LL)     // 16384
#define CLAT  16
#define CC    512
#define NHH   8
#define HDD   64
#define NBLK  4
#define CFF   (4*CC)      // 2048
#define OUTC  8

// -------------------- scratch (device globals, no allocation) --------------------
__device__ float  g_h    [TT*CC];       // residual stream (fp32)
__device__ float  g_a    [TT*CC];       // final LN out (fp32)
__device__ __half g_ah   [TT*CC];       // LN out (fp16, GEMM A operand)
__device__ __half g_qkvh [TT*3*CC];     // qkv (fp16)
__device__ __half g_attnh[TT*CC];       // attention out (fp16)
__device__ __half g_ffnh [TT*CFF];      // fc1 out (fp16)
__device__ float  g_pool [TB*2*CC];
// transposed fp16 weights per block: qkvT(1536x512) oT(512x512) fc1T(2048x512) fc2T(512x2048)
#define WT_QKV_OFF 0
#define WT_O_OFF   786432
#define WT_FC1_OFF 1048576
#define WT_FC2_OFF 2097152
#define WT_BLK     3145728
__device__ __half g_wth [NBLK * WT_BLK];

__device__ __forceinline__ float gelu_tanh(float x) {
    float x3 = x * x * x;
    return 0.5f * x * (1.0f + tanhf(0.7978845608028654f * (x + 0.044715f * x3)));
}

// ==================== PTX helpers (base ISA only) ====================
__device__ __forceinline__ uint32_t smem_u32(const void* p) {
    return (uint32_t)__cvta_generic_to_shared(p);
}
__device__ __forceinline__ void cp_async16(uint32_t saddr, const void* gptr) {
    asm volatile("cp.async.cg.shared.global [%0], [%1], 16;" :: "r"(saddr), "l"(gptr));
}
__device__ __forceinline__ void cp_commit() { asm volatile("cp.async.commit_group;"); }
template<int N> __device__ __forceinline__ void cp_wait() {
    asm volatile("cp.async.wait_group %0;" :: "n"(N));
}
__device__ __forceinline__ void ldsm_x4(uint32_t* r, uint32_t addr) {
    asm volatile("ldmatrix.sync.aligned.m8n8.x4.shared.b16 {%0,%1,%2,%3}, [%4];"
        : "=r"(r[0]), "=r"(r[1]), "=r"(r[2]), "=r"(r[3]) : "r"(addr));
}
__device__ __forceinline__ void ldsm_x4_t(uint32_t* r, uint32_t addr) {
    asm volatile("ldmatrix.sync.aligned.m8n8.x4.trans.shared.b16 {%0,%1,%2,%3}, [%4];"
        : "=r"(r[0]), "=r"(r[1]), "=r"(r[2]), "=r"(r[3]) : "r"(addr));
}
__device__ __forceinline__ void mma_f16(float* d, const uint32_t* a, const uint32_t* b) {
    asm volatile(
        "mma.sync.aligned.m16n8k16.row.col.f32.f16.f16.f32 "
        "{%0,%1,%2,%3}, {%4,%5,%6,%7}, {%8,%9}, {%0,%1,%2,%3};"
        : "+f"(d[0]), "+f"(d[1]), "+f"(d[2]), "+f"(d[3])
        : "r"(a[0]), "r"(a[1]), "r"(a[2]), "r"(a[3]), "r"(b[0]), "r"(b[1]));
}
__device__ __forceinline__ uint32_t packh2(float lo, float hi) {
    __half2 h = __floats2half2_rn(lo, hi);
    return *(uint32_t*)&h;
}

// ==================== fp16 tensor-core GEMM ====================
// C[M,N] = A[M,K](fp16) @ Bt[N,K](fp16)^T + bias (+epilogue).
// CTA 128x128, k-chunk 32, 8 warps (warp tile 64x32). EPI: 0 none, 1 gelu, 2 residual.
// OUT: __half or float. R (fp32) used when EPI==2.
#define GPAD 40   // smem row stride in halves (80B): conflict-free for ldmatrix/cp

template<int EPI, typename OUT>
__global__ __launch_bounds__(256)
void gemm_h_kernel(const __half* __restrict__ A, const __half* __restrict__ Bt,
                   const float* __restrict__ bias, OUT* __restrict__ C,
                   const float* __restrict__ R, int M, int N, int K)
{
    __shared__ __half sA[2][128 * GPAD];
    __shared__ __half sB[2][128 * GPAD];

    const int tid  = threadIdx.x;
    const int lane = tid & 31;
    const int warp = tid >> 5;
    const int warp_m = warp & 1;   // 0..1  (64 rows)
    const int warp_n = warp >> 1;  // 0..3  (32 cols)
    const int g = lane >> 2;       // 0..7
    const int t = lane & 3;        // 0..3

    const int rowbase = blockIdx.y * 128;
    const int colbase = blockIdx.x * 128;
    const int NK = K >> 5;

    float acc[4][4][4];
    #pragma unroll
    for (int mf = 0; mf < 4; mf++)
        #pragma unroll
        for (int nf = 0; nf < 4; nf++)
            #pragma unroll
            for (int j = 0; j < 4; j++) acc[mf][nf][j] = 0.f;

    auto prefetch = [&](int kt) {
        const int buf = kt & 1;
        const __half* Ag = A + (size_t)rowbase * K + kt * 32;
        const __half* Bg = Bt + (size_t)colbase * K + kt * 32;
        uint32_t sa = smem_u32(sA[buf]);
        uint32_t sb = smem_u32(sB[buf]);
        #pragma unroll
        for (int i = 0; i < 2; i++) {
            int u = tid + i * 256;         // 0..511
            int row = u >> 2, q = u & 3;
            cp_async16(sa + row * (GPAD * 2) + q * 16, Ag + (size_t)row * K + q * 8);
        }
        #pragma unroll
        for (int i = 0; i < 2; i++) {
            int u = tid + i * 256;
            int row = u >> 2, q = u & 3;
            cp_async16(sb + row * (GPAD * 2) + q * 16, Bg + (size_t)row * K + q * 8);
        }
    };

    prefetch(0); cp_commit();

    const uint32_t laneoff = (uint32_t)((lane & 15) * (GPAD * 2) + (lane >> 4) * 16);

    for (int kt = 0; kt < NK; kt++) {
        cp_wait<0>();
        __syncthreads();
        if (kt + 1 < NK) { prefetch(kt + 1); cp_commit(); }

        const int buf = kt & 1;
        const uint32_t abase = smem_u32(sA[buf]) + warp_m * 64 * (GPAD * 2) + laneoff;
        const uint32_t bbase = smem_u32(sB[buf]) + warp_n * 32 * (GPAD * 2) + laneoff;

        #pragma unroll
        for (int s = 0; s < 2; s++) {
            uint32_t af[4][4];
            #pragma unroll
            for (int mf = 0; mf < 4; mf++)
                ldsm_x4(af[mf], abase + mf * 16 * (GPAD * 2) + s * 32);
            uint32_t bf[4][2];
            #pragma unroll
            for (int nf2 = 0; nf2 < 2; nf2++) {
                uint32_t r[4];
                ldsm_x4(r, bbase + nf2 * 16 * (GPAD * 2) + s * 32);
                bf[2 * nf2 + 0][0] = r[0]; bf[2 * nf2 + 0][1] = r[2];
                bf[2 * nf2 + 1][0] = r[1]; bf[2 * nf2 + 1][1] = r[3];
            }
            #pragma unroll
            for (int mf = 0; mf < 4; mf++)
                #pragma unroll
                for (int nf = 0; nf < 4; nf++)
                    mma_f16(acc[mf][nf], af[mf], bf[nf]);
        }
        __syncthreads();
    }

    // epilogue
    #pragma unroll
    for (int mf = 0; mf < 4; mf++) {
        const int r0 = rowbase + warp_m * 64 + mf * 16 + g;
        #pragma unroll
        for (int nf = 0; nf < 4; nf++) {
            const int col = colbase + warp_n * 32 + nf * 8 + t * 2;
            const float b0 = __ldg(bias + col);
            const float b1 = __ldg(bias + col + 1);
            #pragma unroll
            for (int half_i = 0; half_i < 2; half_i++) {
                const int r = r0 + half_i * 8;
                float v0 = acc[mf][nf][half_i * 2 + 0] + b0;
                float v1 = acc[mf][nf][half_i * 2 + 1] + b1;
                const size_t idx = (size_t)r * N + col;
                if (EPI == 1) { v0 = gelu_tanh(v0); v1 = gelu_tanh(v1); }
                else if (EPI == 2) {
                    float2 rr = *(const float2*)(R + idx);
                    v0 += rr.x; v1 += rr.y;
                }
                if (sizeof(OUT) == 2) {
                    __half2 h = __floats2half2_rn(v0, v1);
                    *(__half2*)((__half*)C + idx) = h;
                } else {
                    *(float2*)((float*)C + idx) = make_float2(v0, v1);
                }
            }
        }
    }
}

// ==================== fp16 flash attention (mma, online softmax) ====================
// grid (16 q-tiles, 8 heads, 16 batch), 128 threads (4 warps x 16 query rows).
// K-tiles of 64 keys, cp.async double-buffered. Softmax fp32.
#define FPAD 72   // smem row stride in halves (144B)

__global__ __launch_bounds__(128)
void flash_h_kernel(const __half* __restrict__ qkv, __half* __restrict__ o)
{
    __shared__ __half Qs[64 * FPAD];
    __shared__ __half Ks[2][64 * FPAD];
    __shared__ __half Vs[2][64 * FPAD];

    const int tid  = threadIdx.x;
    const int lane = tid & 31;
    const int w    = tid >> 5;
    const int g    = lane >> 2;
    const int t    = lane & 3;
    const int b = blockIdx.z, h = blockIdx.y, qt = blockIdx.x;

    const size_t tok0 = (size_t)b * LL;

    // load Q tile (64 x 64 halves)
    {
        uint32_t sq = smem_u32(Qs);
        #pragma unroll
        for (int i = 0; i < 4; i++) {
            int u = tid + i * 128;          // 0..511
            int row = u >> 3, q = u & 7;
            cp_async16(sq + row * (FPAD * 2) + q * 16,
                       qkv + (tok0 + qt * 64 + row) * 1536 + h * 64 + q * 8);
        }
        cp_commit();
    }
    auto prefetch_kv = [&](int kt) {
        const int buf = kt & 1;
        uint32_t sk = smem_u32(Ks[buf]);
        uint32_t sv = smem_u32(Vs[buf]);
        #pragma unroll
        for (int i = 0; i < 4; i++) {
            int u = tid + i * 128;
            int row = u >> 3, q = u & 7;
            const __half* src = qkv + (tok0 + kt * 64 + row) * 1536 + h * 64 + q * 8;
            cp_async16(sk + row * (FPAD * 2) + q * 16, src + 512);
            cp_async16(sv + row * (FPAD * 2) + q * 16, src + 1024);
        }
    };
    prefetch_kv(0); cp_commit();

    const uint32_t laneoff = (uint32_t)((lane & 15) * (FPAD * 2) + (lane >> 4) * 16);

    uint32_t aq[4][4];
    float m0 = -INFINITY, m1 = -INFINITY, l0 = 0.f, l1 = 0.f;
    float oacc[8][4];
    #pragma unroll
    for (int nf = 0; nf < 8; nf++)
        #pragma unroll
        for (int j = 0; j < 4; j++) oacc[nf][j] = 0.f;

    for (int kt = 0; kt < 16; kt++) {
        cp_wait<0>();
        __syncthreads();
        if (kt + 1 < 16) { prefetch_kv(kt + 1); cp_commit(); }

        if (kt == 0) {
            const uint32_t qb = smem_u32(Qs) + w * 16 * (FPAD * 2) + laneoff;
            #pragma unroll
            for (int s = 0; s < 4; s++) ldsm_x4(aq[s], qb + s * 32);
        }

        const int buf = kt & 1;
        const uint32_t kb = smem_u32(Ks[buf]) + laneoff;
        const uint32_t vb = smem_u32(Vs[buf]) + laneoff;

        // S = Q @ K^T  (16 rows x 64 keys per warp)
        float sacc[8][4];
        #pragma unroll
        for (int nf = 0; nf < 8; nf++)
            #pragma unroll
            for (int j = 0; j < 4; j++) sacc[nf][j] = 0.f;
        #pragma unroll
        for (int s = 0; s < 4; s++) {
            #pragma unroll
            for (int j2 = 0; j2 < 4; j2++) {
                uint32_t r[4];
                ldsm_x4(r, kb + j2 * 16 * (FPAD * 2) + s * 32);
                uint32_t bfr0[2] = { r[0], r[2] };
                uint32_t bfr1[2] = { r[1], r[3] };
                mma_f16(sacc[2 * j2 + 0], aq[s], bfr0);
                mma_f16(sacc[2 * j2 + 1], aq[s], bfr1);
            }
        }

        // online softmax (rows g and g+8)
        float ml0 = -INFINITY, ml1 = -INFINITY;
        #pragma unroll
        for (int nf = 0; nf < 8; nf++) {
            #pragma unroll
            for (int j = 0; j < 4; j++) sacc[nf][j] *= 0.125f;
            ml0 = fmaxf(ml0, fmaxf(sacc[nf][0], sacc[nf][1]));
            ml1 = fmaxf(ml1, fmaxf(sacc[nf][2], sacc[nf][3]));
        }
        ml0 = fmaxf(ml0, __shfl_xor_sync(0xffffffffu, ml0, 1));
        ml0 = fmaxf(ml0, __shfl_xor_sync(0xffffffffu, ml0, 2));
        ml1 = fmaxf(ml1, __shfl_xor_sync(0xffffffffu, ml1, 1));
        ml1 = fmaxf(ml1, __shfl_xor_sync(0xffffffffu, ml1, 2));
        const float mn0 = fmaxf(m0, ml0), mn1 = fmaxf(m1, ml1);
        const float c0 = __expf(m0 - mn0), c1 = __expf(m1 - mn1);

        float ps0 = 0.f, ps1 = 0.f;
        uint32_t ph0[8], ph1[8];
        #pragma unroll
        for (int nf = 0; nf < 8; nf++) {
            float p0 = __expf(sacc[nf][0] - mn0);
            float p1 = __expf(sacc[nf][1] - mn0);
            float p2 = __expf(sacc[nf][2] - mn1);
            float p3 = __expf(sacc[nf][3] - mn1);
            ps0 += p0 + p1; ps1 += p2 + p3;
            ph0[nf] = packh2(p0, p1);
            ph1[nf] = packh2(p2, p3);
        }
        ps0 += __shfl_xor_sync(0xffffffffu, ps0, 1);
        ps0 += __shfl_xor_sync(0xffffffffu, ps0, 2);
        ps1 += __shfl_xor_sync(0xffffffffu, ps1, 1);
        ps1 += __shfl_xor_sync(0xffffffffu, ps1, 2);
        l0 = l0 * c0 + ps0; l1 = l1 * c1 + ps1;
        m0 = mn0; m1 = mn1;
        #pragma unroll
        for (int nf = 0; nf < 8; nf++) {
            oacc[nf][0] *= c0; oacc[nf][1] *= c0;
            oacc[nf][2] *= c1; oacc[nf][3] *= c1;
        }

        // O += P @ V   (P frags come straight from registers)
        #pragma unroll
        for (int kk = 0; kk < 4; kk++) {
            uint32_t pa[4] = { ph0[2 * kk], ph1[2 * kk], ph0[2 * kk + 1], ph1[2 * kk + 1] };
            #pragma unroll
            for (int nf2 = 0; nf2 < 4; nf2++) {
                uint32_t r[4];
                ldsm_x4_t(r, vb + kk * 16 * (FPAD * 2) + nf2 * 32);
                uint32_t bfr0[2] = { r[0], r[1] };
                uint32_t bfr1[2] = { r[2], r[3] };
                mma_f16(oacc[2 * nf2 + 0], pa, bfr0);
                mma_f16(oacc[2 * nf2 + 1], pa, bfr1);
            }
        }
        __syncthreads();
    }

    const float i0 = 1.f / l0, i1 = 1.f / l1;
    const size_t row0 = tok0 + qt * 64 + w * 16 + g;
    #pragma unroll
    for (int nf = 0; nf < 8; nf++) {
        const int col = h * 64 + nf * 8 + t * 2;
        __half2 v0 = __floats2half2_rn(oacc[nf][0] * i0, oacc[nf][1] * i0);
        __half2 v1 = __floats2half2_rn(oacc[nf][2] * i1, oacc[nf][3] * i1);
        *(__half2*)(o + row0 * CC + col)       = v0;
        *(__half2*)(o + (row0 + 8) * CC + col) = v1;
    }
}

// -------------------- weight transpose: W[K,N] fp32 -> Wt[N,K] fp16 --------------
__global__ __launch_bounds__(256)
void transpose_h_kernel(const float* __restrict__ W, __half* __restrict__ Wt, int K, int N)
{
    __shared__ float tbuf[32][33];
    const int n0 = blockIdx.x * 32, k0 = blockIdx.y * 32;
    for (int i = threadIdx.y; i < 32; i += 8)
        tbuf[i][threadIdx.x] = W[(size_t)(k0 + i) * N + n0 + threadIdx.x];
    __syncthreads();
    for (int i = threadIdx.y; i < 32; i += 8)
        Wt[(size_t)(n0 + i) * K + k0 + threadIdx.x] = __float2half_rn(tbuf[threadIdx.x][i]);
}

// -------------------- small SIMT GEMM for input projection (K=16, fp32) ----------
__global__ __launch_bounds__(256)
void gemm_simt_kernel(const float* __restrict__ A, const float* __restrict__ B,
                      const float* __restrict__ bias, float* __restrict__ C,
                      int M, int N, int K)
{
    __shared__ float As[16][128];
    __shared__ float Bs[16][64];
    const int tid = threadIdx.x;
    const int tx = tid & 15, ty = tid >> 4;
    const int row0 = blockIdx.y * 128 + ty * 8;
    const int col0 = blockIdx.x * 64 + tx * 4;

    float acc[8][4];
    #pragma unroll
    for (int i = 0; i < 8; i++)
        #pragma unroll
        for (int j = 0; j < 4; j++) acc[i][j] = 0.f;

    for (int kt = 0; kt < K; kt += 16) {
        for (int i = tid; i < 128 * 16; i += 256) {
            int r = i >> 4, c = i & 15;
            As[c][r] = A[(size_t)(blockIdx.y * 128 + r) * K + kt + c];
        }
        for (int i = tid; i < 16 * 64; i += 256) {
            int r = i >> 6, c = i & 63;
            Bs[r][c] = B[(size_t)(kt + r) * N + blockIdx.x * 64 + c];
        }
        __syncthreads();
        #pragma unroll
        for (int k = 0; k < 16; k++) {
            float a[8], bb[4];
            #pragma unroll
            for (int i = 0; i < 8; i++) a[i] = As[k][ty * 8 + i];
            #pragma unroll
            for (int j = 0; j < 4; j++) bb[j] = Bs[k][tx * 4 + j];
            #pragma unroll
            for (int i = 0; i < 8; i++)
                #pragma unroll
                for (int j = 0; j < 4; j++) acc[i][j] += a[i] * bb[j];
        }
        __syncthreads();
    }
    #pragma unroll
    for (int i = 0; i < 8; i++)
        #pragma unroll
        for (int j = 0; j < 4; j++)
            C[(size_t)(row0 + i) * N + col0 + j] = acc[i][j] + bias[col0 + j];
}

// -------------------- layer norm (row of 512) -----------------------------------
// MODE 0: affine, fp16 out (feeds tensor cores). MODE 1: no affine, fp32 out.
template<int MODE>
__global__ __launch_bounds__(256)
void ln_kernel(const float* __restrict__ x, const float* __restrict__ sc,
               const float* __restrict__ bi, void* __restrict__ yv)
{
    __shared__ float red[8];
    const int row = blockIdx.x;
    const int tid = threadIdx.x;
    const float* xr = x + (size_t)row * CC;

    float v0 = xr[tid], v1 = xr[tid + 256];
    float s = v0 + v1;
    #pragma unroll
    for (int off = 16; off; off >>= 1) s += __shfl_xor_sync(0xffffffffu, s, off);
    if ((tid & 31) == 0) red[tid >> 5] = s;
    __syncthreads();
    float tot = 0.f;
    #pragma unroll
    for (int i = 0; i < 8; i++) tot += red[i];
    float mean = tot * (1.f / 512.f);
    __syncthreads();

    float d0 = v0 - mean, d1 = v1 - mean;
    s = d0 * d0 + d1 * d1;
    #pragma unroll
    for (int off = 16; off; off >>= 1) s += __shfl_xor_sync(0xffffffffu, s, off);
    if ((tid & 31) == 0) red[tid >> 5] = s;
    __syncthreads();
    tot = 0.f;
    #pragma unroll
    for (int i = 0; i < 8; i++) tot += red[i];
    float var = tot * (1.f / 512.f);
    float inv = rsqrtf(var + 1e-5f);

    float r0 = d0 * inv, r1 = d1 * inv;
    if (MODE == 0) {
        r0 = r0 * sc[tid]       + bi[tid];
        r1 = r1 * sc[tid + 256] + bi[tid + 256];
        __half* y = (__half*)yv;
        y[(size_t)row * CC + tid]       = __float2half_rn(r0);
        y[(size_t)row * CC + tid + 256] = __float2half_rn(r1);
    } else {
        float* y = (float*)yv;
        y[(size_t)row * CC + tid]       = r0;
        y[(size_t)row * CC + tid + 256] = r1;
    }
}

// -------------------- segmented mean+max pool -----------------------------------
__global__ __launch_bounds__(128)
void pool_kernel(const float* __restrict__ hf, float* __restrict__ gp)
{
    const int b = blockIdx.x;
    const int c = blockIdx.y * 128 + threadIdx.x;
    const float* p = hf + (size_t)b * LL * CC + c;
    float sum = 0.f, mx = -INFINITY;
    for (int l = 0; l < LL; l++) {
        float v = p[(size_t)l * CC];
        sum += v;
        mx = fmaxf(mx, v);
    }
    gp[b * (2 * CC) + c]      = sum * (1.f / (float)LL);
    gp[b * (2 * CC) + CC + c] = mx;
}

// -------------------- head ------------------------------------------------------
__global__ __launch_bounds__(128)
void head_kernel(const float* __restrict__ gp, const float* __restrict__ W,
                 const float* __restrict__ bh, float* __restrict__ out)
{
    const int tid = threadIdx.x;
    const int b = tid >> 3, o = tid & 7;
    float acc = bh[o];
    const float* gr = gp + b * 1024;
    for (int k = 0; k < 1024; k++) acc += gr[k] * W[k * 8 + o];
    out[b * 8 + o] = acc;
}

// -------------------- host launch -----------------------------------------------
static void* sym_addr(const void* sym) {
    void* p = nullptr;
    cudaGetSymbolAddress(&p, sym);
    return p;
}

extern "C" void kernel_launch(void* const* d_in, const int* in_sizes, int n_in,
                              void* d_out, int out_size)
{
    const float* feats  = (const float*)d_in[0];
    // d_in[1] = batch_idx (equal segments by construction) — unused
    const float* W_in   = (const float*)d_in[2];
    const float* b_in   = (const float*)d_in[3];
    const float* ln1_s  = (const float*)d_in[4];
    const float* ln1_b  = (const float*)d_in[5];
    const float* W_qkv  = (const float*)d_in[6];
    const float* b_qkv  = (const float*)d_in[7];
    const float* W_o    = (const float*)d_in[8];
    const float* b_o    = (const float*)d_in[9];
    const float* ln2_s  = (const float*)d_in[10];
    const float* ln2_b  = (const float*)d_in[11];
    const float* W_fc1  = (const float*)d_in[12];
    const float* b_fc1  = (const float*)d_in[13];
    const float* W_fc2  = (const float*)d_in[14];
    const float* b_fc2  = (const float*)d_in[15];
    const float* W_head = (const float*)d_in[16];
    const float* b_head = (const float*)d_in[17];
    float* out = (float*)d_out;

    float*  h     = (float*)sym_addr(g_h);
    float*  a     = (float*)sym_addr(g_a);
    __half* ah    = (__half*)sym_addr(g_ah);
    __half* qkvh  = (__half*)sym_addr(g_qkvh);
    __half* attnh = (__half*)sym_addr(g_attnh);
    __half* ffnh  = (__half*)sym_addr(g_ffnh);
    float*  pool  = (float*)sym_addr(g_pool);
    __half* wt    = (__half*)sym_addr(g_wth);

    // transpose + fp16-round all weights
    dim3 tb(32, 8);
    for (int i = 0; i < NBLK; i++) {
        __half* wb = wt + (size_t)i * WT_BLK;
        transpose_h_kernel<<<dim3(1536/32, 512/32), tb>>>(W_qkv + (size_t)i*CC*3*CC, wb + WT_QKV_OFF, 512, 1536);
        transpose_h_kernel<<<dim3( 512/32, 512/32), tb>>>(W_o   + (size_t)i*CC*CC,   wb + WT_O_OFF,   512,  512);
        transpose_h_kernel<<<dim3(2048/32, 512/32), tb>>>(W_fc1 + (size_t)i*CC*CFF,  wb + WT_FC1_OFF, 512, 2048);
        transpose_h_kernel<<<dim3( 512/32,2048/32), tb>>>(W_fc2 + (size_t)i*CFF*CC,  wb + WT_FC2_OFF, 2048, 512);
    }

    // input projection: h = feats @ W_in + b_in   [16384,16]x[16,512] (fp32)
    gemm_simt_kernel<<<dim3(CC/64, TT/128), 256>>>(feats, W_in, b_in, h, TT, CC, CLAT);

    for (int i = 0; i < NBLK; i++) {
        __half* wb = wt + (size_t)i * WT_BLK;
        ln_kernel<0><<<TT, 256>>>(h, ln1_s + i * CC, ln1_b + i * CC, ah);
        gemm_h_kernel<0, __half><<<dim3(12, 128), 256>>>(
            ah, wb + WT_QKV_OFF, b_qkv + i * 3 * CC, qkvh, nullptr, TT, 3 * CC, CC);
        flash_h_kernel<<<dim3(16, NHH, TB), 128>>>(qkvh, attnh);
        gemm_h_kernel<2, float><<<dim3(4, 128), 256>>>(
            attnh, wb + WT_O_OFF, b_o + i * CC, h, h, TT, CC, CC);
        ln_kernel<0><<<TT, 256>>>(h, ln2_s + i * CC, ln2_b + i * CC, ah);
        gemm_h_kernel<1, __half><<<dim3(16, 128), 256>>>(
            ah, wb + WT_FC1_OFF, b_fc1 + i * CFF, ffnh, nullptr, TT, CFF, CC);
        gemm_h_kernel<2, float><<<dim3(4, 128), 256>>>(
            ffnh, wb + WT_FC2_OFF, b_fc2 + i * CC, h, h, TT, CC, CFF);
    }

    ln_kernel<1><<<TT, 256>>>(h, nullptr, nullptr, a);
    pool_kernel<<<dim3(TB, CC / 128), 128>>>(a, pool);
    head_kernel<<<1, 128>>>(pool, W_head, b_head, out);
    (void)in_sizes; (void)n_in; (void)out_size;
}